// round 2
// baseline (speedup 1.0000x reference)
#include <cuda_runtime.h>
#include <cstddef>

// Problem constants
#define Bc  2
#define Sc  2048
#define Hc  1024
#define NHc 16
#define DKc 64
#define Mc  (Bc * Sc)   // 4096

typedef unsigned long long ull;

// ---------------- packed f32x2 helpers (sm_103a) ----------------
__device__ __forceinline__ ull pack2(float x, float y) {
    ull r; asm("mov.b64 %0, {%1, %2};" : "=l"(r) : "f"(x), "f"(y)); return r;
}
__device__ __forceinline__ float2 unpack2(ull v) {
    float2 f; asm("mov.b64 {%0, %1}, %2;" : "=f"(f.x), "=f"(f.y) : "l"(v)); return f;
}
__device__ __forceinline__ void fma2(ull& d, ull a, ull b) {
    asm("fma.rn.f32x2 %0, %1, %2, %0;" : "+l"(d) : "l"(a), "l"(b));
}
__device__ __forceinline__ ull mul2(ull a, ull b) {
    ull d; asm("mul.rn.f32x2 %0, %1, %2;" : "=l"(d) : "l"(a), "l"(b)); return d;
}

// ---------------- device scratch (allocation-free) ----------------
__device__ float g_qh[Bc * NHc * Sc * DKc];   // [b][h][s][d]
__device__ float g_kh[Bc * NHc * Sc * DKc];
__device__ float g_vh[Bc * NHc * Sc * DKc];
__device__ float g_ctx[Bc * Sc * Hc];         // [b][s][h*DK+d]

// ======================================================================
// GEMM: C[m][n] = X[m][:] . W[n][:] + bias[n]
// M = 4096, N = K = 1024. BM=BN=128, BK=16, 256 threads, 8x8 per thread.
// HEAD=1: write into [B][NH][S][DK] layout; HEAD=0: flat [M][N].
// ======================================================================
#define GBM 128
#define GBN 128
#define GBK 16

template <int HEAD>
__global__ void __launch_bounds__(256) gemm_kernel(
    const float* __restrict__ X, const float* __restrict__ W,
    const float* __restrict__ bias, float* __restrict__ C)
{
    __shared__ float As[GBK][GBM + 4];
    __shared__ float Bs[GBK][GBN + 4];

    const int tid = threadIdx.x;
    const int tx = tid & 15;
    const int ty = tid >> 4;
    const int m0 = blockIdx.y * GBM;
    const int n0 = blockIdx.x * GBN;
    const int K = Hc;

    ull acc[8][4] = {};

    for (int k0 = 0; k0 < K; k0 += GBK) {
#pragma unroll
        for (int it = 0; it < 2; it++) {
            int idx = tid + it * 256;          // 0..511 float4 tiles
            int row = idx >> 2;                // 0..127
            int kc  = (idx & 3) * 4;           // 0,4,8,12
            float4 a = *(const float4*)(X + (size_t)(m0 + row) * K + k0 + kc);
            As[kc + 0][row] = a.x; As[kc + 1][row] = a.y;
            As[kc + 2][row] = a.z; As[kc + 3][row] = a.w;
            float4 w = *(const float4*)(W + (size_t)(n0 + row) * K + k0 + kc);
            Bs[kc + 0][row] = w.x; Bs[kc + 1][row] = w.y;
            Bs[kc + 2][row] = w.z; Bs[kc + 3][row] = w.w;
        }
        __syncthreads();

#pragma unroll
        for (int k = 0; k < GBK; k++) {
            float4 a0 = *(const float4*)&As[k][ty * 4];
            float4 a1 = *(const float4*)&As[k][64 + ty * 4];
            float4 b0 = *(const float4*)&Bs[k][tx * 4];
            float4 b1 = *(const float4*)&Bs[k][64 + tx * 4];
            ull bp0 = pack2(b0.x, b0.y);
            ull bp1 = pack2(b0.z, b0.w);
            ull bp2 = pack2(b1.x, b1.y);
            ull bp3 = pack2(b1.z, b1.w);
            float av[8] = {a0.x, a0.y, a0.z, a0.w, a1.x, a1.y, a1.z, a1.w};
#pragma unroll
            for (int i = 0; i < 8; i++) {
                ull ad = pack2(av[i], av[i]);
                fma2(acc[i][0], ad, bp0);
                fma2(acc[i][1], ad, bp1);
                fma2(acc[i][2], ad, bp2);
                fma2(acc[i][3], ad, bp3);
            }
        }
        __syncthreads();
    }

    // epilogue: bias + store (float4, d-contiguous in both layouts)
#pragma unroll
    for (int i = 0; i < 8; i++) {
        int m = m0 + ((i < 4) ? (ty * 4 + i) : (64 + ty * 4 + (i - 4)));
#pragma unroll
        for (int jj = 0; jj < 2; jj++) {
            int n = n0 + jj * 64 + tx * 4;
            float4 bi = *(const float4*)(bias + n);
            float2 c0 = unpack2(acc[i][jj * 2 + 0]);
            float2 c1 = unpack2(acc[i][jj * 2 + 1]);
            float4 r = make_float4(c0.x + bi.x, c0.y + bi.y, c1.x + bi.z, c1.y + bi.w);
            if (HEAD) {
                int bb = m >> 11;          // / Sc
                int s  = m & (Sc - 1);
                int hh = n >> 6;           // / DKc
                int d  = n & (DKc - 1);
                *(float4*)(C + ((((size_t)bb * NHc + hh) * Sc + s) * DKc) + d) = r;
            } else {
                *(float4*)(C + (size_t)m * Hc + n) = r;
            }
        }
    }
}

// ======================================================================
// Flash attention: per (q-tile 64, head, batch). DK=64, K-tiles of 64.
// smem arrays stride 68 floats (bank-conflict-free patterns).
// ======================================================================
#define ASTR 68
#define ATTN_SMEM (3 * 64 * ASTR * (int)sizeof(float))   // 52224 bytes

__global__ void __launch_bounds__(256) attn_kernel(
    const float* __restrict__ Q, const float* __restrict__ K,
    const float* __restrict__ V, float* __restrict__ O)
{
    extern __shared__ float sm[];
    float* Qs = sm;                    // [64][68]  straight [i][d]
    float* KP = sm + 64 * ASTR;        // [64][68]  Ks [j][d], reused as Pt [j][i]
    float* Vs = sm + 2 * 64 * ASTR;    // [64][68]  straight [j][d]

    const int tid = threadIdx.x;
    const int tx = tid & 15;
    const int ty = tid >> 4;
    const int qb = blockIdx.x;
    const int h  = blockIdx.y;
    const int b  = blockIdx.z;

    const float* qp = Q + (((size_t)b * NHc + h) * Sc + (size_t)qb * 64) * DKc;
    const float* kb = K + ((size_t)b * NHc + h) * Sc * DKc;
    const float* vb = V + ((size_t)b * NHc + h) * Sc * DKc;

    // load Q tile (64 x 64), straight, float4
#pragma unroll
    for (int t = 0; t < 4; t++) {
        int v4 = tid + t * 256;
        int i  = v4 >> 4;
        int dv = (v4 & 15) * 4;
        *(float4*)&Qs[i * ASTR + dv] = *(const float4*)(qp + i * DKc + dv);
    }

    ull o2[4][2] = {};
    float m[4], l[4];
#pragma unroll
    for (int r = 0; r < 4; r++) { m[r] = -INFINITY; l[r] = 0.0f; }

    for (int kt = 0; kt < Sc / 64; kt++) {
        __syncthreads();   // prev-iter PV done reading KP/Vs (and Q load on iter 0)
        const float* kp = kb + (size_t)kt * 64 * DKc;
        const float* vp = vb + (size_t)kt * 64 * DKc;
#pragma unroll
        for (int t = 0; t < 4; t++) {
            int v4 = tid + t * 256;
            int j  = v4 >> 4;
            int dv = (v4 & 15) * 4;
            *(float4*)&KP[j * ASTR + dv] = *(const float4*)(kp + j * DKc + dv);
            *(float4*)&Vs[j * ASTR + dv] = *(const float4*)(vp + j * DKc + dv);
        }
        __syncthreads();

        // S = Q K^T : rows i = 4*ty+r, cols j = tx + 16*c
        ull s2[4][2] = {};
#pragma unroll 4
        for (int d = 0; d < DKc; d++) {
            float k0 = KP[(tx)      * ASTR + d];
            float k1 = KP[(tx + 16) * ASTR + d];
            float k2 = KP[(tx + 32) * ASTR + d];
            float k3 = KP[(tx + 48) * ASTR + d];
            ull kp01 = pack2(k0, k1);
            ull kp23 = pack2(k2, k3);
#pragma unroll
            for (int r = 0; r < 4; r++) {
                float qv = Qs[(4 * ty + r) * ASTR + d];
                ull qd = pack2(qv, qv);
                fma2(s2[r][0], qd, kp01);
                fma2(s2[r][1], qd, kp23);
            }
        }

        // unpack + scale by 1/sqrt(DK)
        float sv[4][4];
#pragma unroll
        for (int r = 0; r < 4; r++) {
            float2 u0 = unpack2(s2[r][0]);
            float2 u1 = unpack2(s2[r][1]);
            sv[r][0] = u0.x * 0.125f; sv[r][1] = u0.y * 0.125f;
            sv[r][2] = u1.x * 0.125f; sv[r][3] = u1.y * 0.125f;
        }

        // online softmax (row reductions across the 16 tx lanes)
#pragma unroll
        for (int r = 0; r < 4; r++) {
            float mx = fmaxf(fmaxf(sv[r][0], sv[r][1]), fmaxf(sv[r][2], sv[r][3]));
#pragma unroll
            for (int off = 8; off > 0; off >>= 1)
                mx = fmaxf(mx, __shfl_xor_sync(0xffffffffu, mx, off));
            float mn = fmaxf(m[r], mx);
            float alpha = __expf(m[r] - mn);
            m[r] = mn;
            float rs = 0.0f;
#pragma unroll
            for (int c = 0; c < 4; c++) {
                sv[r][c] = __expf(sv[r][c] - mn);
                rs += sv[r][c];
            }
#pragma unroll
            for (int off = 8; off > 0; off >>= 1)
                rs += __shfl_xor_sync(0xffffffffu, rs, off);
            l[r] = l[r] * alpha + rs;
            ull ad = pack2(alpha, alpha);
            o2[r][0] = mul2(o2[r][0], ad);
            o2[r][1] = mul2(o2[r][1], ad);
        }

        __syncthreads();   // all S reads of KP(Ks) done
        // write P transposed: Pt[j][i], j = tx+16c, i = 4ty..4ty+3 (float4)
#pragma unroll
        for (int c = 0; c < 4; c++) {
            float4 t = make_float4(sv[0][c], sv[1][c], sv[2][c], sv[3][c]);
            *(float4*)&KP[(tx + 16 * c) * ASTR + 4 * ty] = t;
        }
        __syncthreads();

        // O += P @ V : O[i][dd], dd = 4*tx + c
#pragma unroll 4
        for (int j = 0; j < 64; j++) {
            float4 p  = *(const float4*)&KP[j * ASTR + 4 * ty];
            float4 vv = *(const float4*)&Vs[j * ASTR + 4 * tx];
            ull v01 = pack2(vv.x, vv.y);
            ull v23 = pack2(vv.z, vv.w);
            float pr[4] = {p.x, p.y, p.z, p.w};
#pragma unroll
            for (int r = 0; r < 4; r++) {
                ull pd = pack2(pr[r], pr[r]);
                fma2(o2[r][0], pd, v01);
                fma2(o2[r][1], pd, v23);
            }
        }
    }

    // epilogue: normalize and write ctx in concat layout [b][s][h*DK+d]
#pragma unroll
    for (int r = 0; r < 4; r++) {
        float inv = 1.0f / l[r];
        float2 u0 = unpack2(o2[r][0]);
        float2 u1 = unpack2(o2[r][1]);
        float4 res = make_float4(u0.x * inv, u0.y * inv, u1.x * inv, u1.y * inv);
        int srow = qb * 64 + 4 * ty + r;
        *(float4*)(O + ((size_t)b * Sc + srow) * Hc + h * DKc + 4 * tx) = res;
    }
}

// ======================================================================
// launch
// ======================================================================
extern "C" void kernel_launch(void* const* d_in, const int* in_sizes, int n_in,
                              void* d_out, int out_size)
{
    (void)in_sizes; (void)n_in; (void)out_size;

    const float* q  = (const float*)d_in[0];
    const float* v  = (const float*)d_in[1];
    const float* k  = (const float*)d_in[2];
    const float* Wq = (const float*)d_in[3];
    const float* bq = (const float*)d_in[4];
    const float* Wk = (const float*)d_in[5];
    const float* bk = (const float*)d_in[6];
    const float* Wv = (const float*)d_in[7];
    const float* bv = (const float*)d_in[8];
    const float* Wo = (const float*)d_in[9];
    const float* bo = (const float*)d_in[10];

    float *qh, *kh, *vh, *ctx;
    cudaGetSymbolAddress((void**)&qh,  g_qh);
    cudaGetSymbolAddress((void**)&kh,  g_kh);
    cudaGetSymbolAddress((void**)&vh,  g_vh);
    cudaGetSymbolAddress((void**)&ctx, g_ctx);

    // >48KB dynamic smem opt-in (attribute set, not a stream op; capture-safe)
    cudaFuncSetAttribute(attn_kernel, cudaFuncAttributeMaxDynamicSharedMemorySize,
                         ATTN_SMEM);

    dim3 ggrid(Hc / GBN, Mc / GBM);   // (8, 32)

    gemm_kernel<1><<<ggrid, 256>>>(q, Wq, bq, qh);
    gemm_kernel<1><<<ggrid, 256>>>(k, Wk, bk, kh);
    gemm_kernel<1><<<ggrid, 256>>>(v, Wv, bv, vh);

    attn_kernel<<<dim3(Sc / 64, NHc, Bc), 256, ATTN_SMEM>>>(qh, kh, vh, ctx);

    gemm_kernel<0><<<ggrid, 256>>>(ctx, Wo, bo, (float*)d_out);
}

// round 4
// speedup vs baseline: 1.3400x; 1.3400x over previous
#include <cuda_runtime.h>
#include <cuda_bf16.h>
#include <cstdint>
#include <cstddef>

// Problem constants
#define Bc  2
#define Sc  2048
#define Hc  1024
#define NHc 16
#define DKc 64
#define Mc  (Bc * Sc)   // 4096

typedef unsigned long long ull;

// ---------------- packed f32x2 helpers (sm_103a) ----------------
__device__ __forceinline__ ull pack2(float x, float y) {
    ull r; asm("mov.b64 %0, {%1, %2};" : "=l"(r) : "f"(x), "f"(y)); return r;
}
__device__ __forceinline__ float2 unpack2(ull v) {
    float2 f; asm("mov.b64 {%0, %1}, %2;" : "=f"(f.x), "=f"(f.y) : "l"(v)); return f;
}
__device__ __forceinline__ void fma2(ull& d, ull a, ull b) {
    asm("fma.rn.f32x2 %0, %1, %2, %0;" : "+l"(d) : "l"(a), "l"(b));
}
__device__ __forceinline__ ull mul2(ull a, ull b) {
    ull d; asm("mul.rn.f32x2 %0, %1, %2;" : "=l"(d) : "l"(a), "l"(b)); return d;
}

// ---------------- mma.sync helpers (sm_80+ path, legal on compute_103) ----
__device__ __forceinline__ uint32_t smem_u32(const void* p) {
    uint32_t a;
    asm("{ .reg .u64 t; cvta.to.shared.u64 t, %1; cvt.u32.u64 %0, t; }" : "=r"(a) : "l"(p));
    return a;
}
__device__ __forceinline__ void ldsm_x4(uint32_t* r, uint32_t a) {
    asm volatile("ldmatrix.sync.aligned.m8n8.x4.shared.b16 {%0,%1,%2,%3}, [%4];"
        : "=r"(r[0]), "=r"(r[1]), "=r"(r[2]), "=r"(r[3]) : "r"(a));
}
__device__ __forceinline__ void ldsm_x2(uint32_t* r, uint32_t a) {
    asm volatile("ldmatrix.sync.aligned.m8n8.x2.shared.b16 {%0,%1}, [%2];"
        : "=r"(r[0]), "=r"(r[1]) : "r"(a));
}
__device__ __forceinline__ void mma16816(float* c, const uint32_t* a, const uint32_t* b) {
    asm volatile("mma.sync.aligned.m16n8k16.row.col.f32.bf16.bf16.f32 "
        "{%0,%1,%2,%3}, {%4,%5,%6,%7}, {%8,%9}, {%0,%1,%2,%3};"
        : "+f"(c[0]), "+f"(c[1]), "+f"(c[2]), "+f"(c[3])
        : "r"(a[0]), "r"(a[1]), "r"(a[2]), "r"(a[3]), "r"(b[0]), "r"(b[1]));
}
__device__ __forceinline__ void cp_async16(uint32_t dst, const void* src) {
    asm volatile("cp.async.cg.shared.global [%0], [%1], 16;" :: "r"(dst), "l"(src));
}
#define CP_COMMIT() asm volatile("cp.async.commit_group;" ::: "memory")
#define CP_WAIT1()  asm volatile("cp.async.wait_group 1;" ::: "memory")

// ---------------- device scratch (allocation-free) ----------------
__device__ float g_qh[Bc * NHc * Sc * DKc];   // [b][h][s][d]
__device__ float g_kh[Bc * NHc * Sc * DKc];
__device__ float g_vh[Bc * NHc * Sc * DKc];
__device__ float g_ctx[Bc * Sc * Hc];         // [b][s][h*DK+d]
__device__ __nv_bfloat16 g_Ah[Mc * Hc];
__device__ __nv_bfloat16 g_Al[Mc * Hc];
__device__ __nv_bfloat16 g_Wh[Hc * Hc];
__device__ __nv_bfloat16 g_Wl[Hc * Hc];

// ======================================================================
// fp32 -> bf16 hi/lo split
// ======================================================================
__global__ void split_kernel(const float* __restrict__ x,
                             __nv_bfloat16* __restrict__ hi,
                             __nv_bfloat16* __restrict__ lo, int n4)
{
    int i = blockIdx.x * blockDim.x + threadIdx.x;
    if (i >= n4) return;
    float4 v = ((const float4*)x)[i];
    __nv_bfloat16 h0 = __float2bfloat16(v.x);
    __nv_bfloat16 h1 = __float2bfloat16(v.y);
    __nv_bfloat16 h2 = __float2bfloat16(v.z);
    __nv_bfloat16 h3 = __float2bfloat16(v.w);
    __nv_bfloat162 ha; ha.x = h0; ha.y = h1;
    __nv_bfloat162 hb; hb.x = h2; hb.y = h3;
    ((__nv_bfloat162*)hi)[2 * i]     = ha;
    ((__nv_bfloat162*)hi)[2 * i + 1] = hb;
    __nv_bfloat162 la, lb;
    la.x = __float2bfloat16(v.x - __bfloat162float(h0));
    la.y = __float2bfloat16(v.y - __bfloat162float(h1));
    lb.x = __float2bfloat16(v.z - __bfloat162float(h2));
    lb.y = __float2bfloat16(v.w - __bfloat162float(h3));
    ((__nv_bfloat162*)lo)[2 * i]     = la;
    ((__nv_bfloat162*)lo)[2 * i + 1] = lb;
}

// ======================================================================
// mma.sync GEMM: C[m][n] = A[m][:].W[n][:] + bias[n], 3-MMA bf16 split.
// CTA 128x128, 8 warps (2x4), warp tile 64x32, BK=32, double-buffered.
// SMEM row stride 40 bf16 (80B) -> ldmatrix conflict-free.
// HEAD=1: write [B][NH][S][DK]; HEAD=0: flat [M][Hc].
// ======================================================================
#define MSTR 40                         // bf16 elems per smem row
#define TILE_B (128 * MSTR * 2)         // 10240 bytes per tile
#define STAGE_B (4 * TILE_B)            // Ah, Al, Wh, Wl
#define GEMM_SMEM (2 * STAGE_B)         // 81920 bytes

template <int HEAD>
__global__ void __launch_bounds__(256, 1) gemm_mma(
    const __nv_bfloat16* __restrict__ Ah, const __nv_bfloat16* __restrict__ Al,
    const __nv_bfloat16* __restrict__ Bh, const __nv_bfloat16* __restrict__ Bl,
    const float* __restrict__ bias, float* __restrict__ C)
{
    extern __shared__ char smem[];
    const uint32_t sb = smem_u32(smem);
    const int tid = threadIdx.x;
    const int wid = tid >> 5;
    const int lid = tid & 31;
    const int wm = (wid >> 2) * 64;     // warp m offset in tile
    const int wn = (wid & 3) * 32;      // warp n offset in tile
    const int m0 = blockIdx.y * 128;
    const int n0 = blockIdx.x * 128;

    const __nv_bfloat16* gsrc[4] = {
        Ah + (size_t)m0 * Hc, Al + (size_t)m0 * Hc,
        Bh + (size_t)n0 * Hc, Bl + (size_t)n0 * Hc };

    // per-thread load coords: 512 16B-chunks per tile, 2 per thread
    const int r0 = tid >> 2;            // rows tid/4 and tid/4+64
    const int c0 = tid & 3;             // 16B chunk in row (4 per row)

    auto stage_load = [&](int stage, int it) {
        uint32_t base = sb + stage * STAGE_B;
#pragma unroll
        for (int a = 0; a < 4; a++) {
            const __nv_bfloat16* s = gsrc[a] + it * 32;
#pragma unroll
            for (int rep = 0; rep < 2; rep++) {
                int row = r0 + rep * 64;
                cp_async16(base + a * TILE_B + row * (MSTR * 2) + c0 * 16,
                           s + (size_t)row * Hc + c0 * 8);
            }
        }
    };

    float acc[4][4][4] = {};            // [mt][nt][frag]

    stage_load(0, 0);
    CP_COMMIT();

    for (int it = 0; it < 32; it++) {
        if (it + 1 < 32) stage_load((it + 1) & 1, it + 1);
        CP_COMMIT();
        CP_WAIT1();
        __syncthreads();

        const uint32_t st = sb + (it & 1) * STAGE_B;
        const uint32_t sAh = st;
        const uint32_t sAl = st + TILE_B;
        const uint32_t sBh = st + 2 * TILE_B;
        const uint32_t sBl = st + 3 * TILE_B;

#pragma unroll
        for (int ks = 0; ks < 2; ks++) {
            const int k0 = ks * 16;
            // A fragments: rows wm + mt*16 + (lid&15), khalf (lid>>4)*8
            uint32_t ah[4][4], al[4][4];
            const int ar = wm + (lid & 15);
            const int ak = k0 + ((lid >> 4) << 3);
#pragma unroll
            for (int mt = 0; mt < 4; mt++) {
                uint32_t off = (uint32_t)((ar + mt * 16) * MSTR + ak) * 2;
                ldsm_x4(ah[mt], sAh + off);
                ldsm_x4(al[mt], sAl + off);
            }
            // B fragments: rows wn + nt*8 + (lid&7), khalf ((lid>>3)&1)*8
            uint32_t bh[4][2], bl[4][2];
            const int br = wn + (lid & 7);
            const int bk = k0 + (((lid >> 3) & 1) << 3);
#pragma unroll
            for (int nt = 0; nt < 4; nt++) {
                uint32_t off = (uint32_t)((br + nt * 8) * MSTR + bk) * 2;
                ldsm_x2(bh[nt], sBh + off);
                ldsm_x2(bl[nt], sBl + off);
            }
#pragma unroll
            for (int mt = 0; mt < 4; mt++) {
#pragma unroll
                for (int nt = 0; nt < 4; nt++) {
                    mma16816(acc[mt][nt], ah[mt], bh[nt]);
                    mma16816(acc[mt][nt], al[mt], bh[nt]);
                    mma16816(acc[mt][nt], ah[mt], bl[nt]);
                }
            }
        }
        __syncthreads();
    }

    // epilogue: C frag (mt,nt): c0,c1 @ (row, n..n+1), c2,c3 @ (row+8, n..n+1)
    const int erow = (lid >> 2);
    const int ecol = (lid & 3) * 2;
#pragma unroll
    for (int mt = 0; mt < 4; mt++) {
#pragma unroll
        for (int nt = 0; nt < 4; nt++) {
            int m = m0 + wm + mt * 16 + erow;
            int n = n0 + wn + nt * 8 + ecol;
            float2 bi = *(const float2*)(bias + n);
            float2 v0 = make_float2(acc[mt][nt][0] + bi.x, acc[mt][nt][1] + bi.y);
            float2 v1 = make_float2(acc[mt][nt][2] + bi.x, acc[mt][nt][3] + bi.y);
            if (HEAD) {
                int hh = n >> 6, d = n & (DKc - 1);
                int bb = m >> 11, s = m & (Sc - 1);
                size_t base = (((size_t)bb * NHc + hh) * Sc);
                *(float2*)(C + (base + s) * DKc + d) = v0;
                int m2 = m + 8;
                int bb2 = m2 >> 11, s2 = m2 & (Sc - 1);
                *(float2*)(C + ((((size_t)bb2 * NHc + hh) * Sc) + s2) * DKc + d) = v1;
            } else {
                *(float2*)(C + (size_t)m * Hc + n) = v0;
                *(float2*)(C + (size_t)(m + 8) * Hc + n) = v1;
            }
        }
    }
}

// ======================================================================
// Flash attention (unchanged, fp32 SIMT + f32x2)
// ======================================================================
#define ASTR 68
#define ATTN_SMEM (3 * 64 * ASTR * (int)sizeof(float))   // 52224 bytes

__global__ void __launch_bounds__(256) attn_kernel(
    const float* __restrict__ Q, const float* __restrict__ K,
    const float* __restrict__ V, float* __restrict__ O)
{
    extern __shared__ float sm[];
    float* Qs = sm;
    float* KP = sm + 64 * ASTR;
    float* Vs = sm + 2 * 64 * ASTR;

    const int tid = threadIdx.x;
    const int tx = tid & 15;
    const int ty = tid >> 4;
    const int qb = blockIdx.x;
    const int h  = blockIdx.y;
    const int b  = blockIdx.z;

    const float* qp = Q + (((size_t)b * NHc + h) * Sc + (size_t)qb * 64) * DKc;
    const float* kb = K + ((size_t)b * NHc + h) * Sc * DKc;
    const float* vb = V + ((size_t)b * NHc + h) * Sc * DKc;

#pragma unroll
    for (int t = 0; t < 4; t++) {
        int v4 = tid + t * 256;
        int i  = v4 >> 4;
        int dv = (v4 & 15) * 4;
        *(float4*)&Qs[i * ASTR + dv] = *(const float4*)(qp + i * DKc + dv);
    }

    ull o2[4][2] = {};
    float m[4], l[4];
#pragma unroll
    for (int r = 0; r < 4; r++) { m[r] = -INFINITY; l[r] = 0.0f; }

    for (int kt = 0; kt < Sc / 64; kt++) {
        __syncthreads();
        const float* kp = kb + (size_t)kt * 64 * DKc;
        const float* vp = vb + (size_t)kt * 64 * DKc;
#pragma unroll
        for (int t = 0; t < 4; t++) {
            int v4 = tid + t * 256;
            int j  = v4 >> 4;
            int dv = (v4 & 15) * 4;
            *(float4*)&KP[j * ASTR + dv] = *(const float4*)(kp + j * DKc + dv);
            *(float4*)&Vs[j * ASTR + dv] = *(const float4*)(vp + j * DKc + dv);
        }
        __syncthreads();

        ull s2[4][2] = {};
#pragma unroll 4
        for (int d = 0; d < DKc; d++) {
            float k0 = KP[(tx)      * ASTR + d];
            float k1 = KP[(tx + 16) * ASTR + d];
            float k2 = KP[(tx + 32) * ASTR + d];
            float k3 = KP[(tx + 48) * ASTR + d];
            ull kp01 = pack2(k0, k1);
            ull kp23 = pack2(k2, k3);
#pragma unroll
            for (int r = 0; r < 4; r++) {
                float qv = Qs[(4 * ty + r) * ASTR + d];
                ull qd = pack2(qv, qv);
                fma2(s2[r][0], qd, kp01);
                fma2(s2[r][1], qd, kp23);
            }
        }

        float sv[4][4];
#pragma unroll
        for (int r = 0; r < 4; r++) {
            float2 u0 = unpack2(s2[r][0]);
            float2 u1 = unpack2(s2[r][1]);
            sv[r][0] = u0.x * 0.125f; sv[r][1] = u0.y * 0.125f;
            sv[r][2] = u1.x * 0.125f; sv[r][3] = u1.y * 0.125f;
        }

#pragma unroll
        for (int r = 0; r < 4; r++) {
            float mx = fmaxf(fmaxf(sv[r][0], sv[r][1]), fmaxf(sv[r][2], sv[r][3]));
#pragma unroll
            for (int off = 8; off > 0; off >>= 1)
                mx = fmaxf(mx, __shfl_xor_sync(0xffffffffu, mx, off));
            float mn = fmaxf(m[r], mx);
            float alpha = __expf(m[r] - mn);
            m[r] = mn;
            float rs = 0.0f;
#pragma unroll
            for (int c = 0; c < 4; c++) {
                sv[r][c] = __expf(sv[r][c] - mn);
                rs += sv[r][c];
            }
#pragma unroll
            for (int off = 8; off > 0; off >>= 1)
                rs += __shfl_xor_sync(0xffffffffu, rs, off);
            l[r] = l[r] * alpha + rs;
            ull ad = pack2(alpha, alpha);
            o2[r][0] = mul2(o2[r][0], ad);
            o2[r][1] = mul2(o2[r][1], ad);
        }

        __syncthreads();
#pragma unroll
        for (int c = 0; c < 4; c++) {
            float4 t = make_float4(sv[0][c], sv[1][c], sv[2][c], sv[3][c]);
            *(float4*)&KP[(tx + 16 * c) * ASTR + 4 * ty] = t;
        }
        __syncthreads();

#pragma unroll 4
        for (int j = 0; j < 64; j++) {
            float4 p  = *(const float4*)&KP[j * ASTR + 4 * ty];
            float4 vv = *(const float4*)&Vs[j * ASTR + 4 * tx];
            ull v01 = pack2(vv.x, vv.y);
            ull v23 = pack2(vv.z, vv.w);
            float pr[4] = {p.x, p.y, p.z, p.w};
#pragma unroll
            for (int r = 0; r < 4; r++) {
                ull pd = pack2(pr[r], pr[r]);
                fma2(o2[r][0], pd, v01);
                fma2(o2[r][1], pd, v23);
            }
        }
    }

#pragma unroll
    for (int r = 0; r < 4; r++) {
        float inv = 1.0f / l[r];
        float2 u0 = unpack2(o2[r][0]);
        float2 u1 = unpack2(o2[r][1]);
        float4 res = make_float4(u0.x * inv, u0.y * inv, u1.x * inv, u1.y * inv);
        int srow = qb * 64 + 4 * ty + r;
        *(float4*)(O + ((size_t)b * Sc + srow) * Hc + h * DKc + 4 * tx) = res;
    }
}

// ======================================================================
// launch
// ======================================================================
extern "C" void kernel_launch(void* const* d_in, const int* in_sizes, int n_in,
                              void* d_out, int out_size)
{
    (void)in_sizes; (void)n_in; (void)out_size;

    const float* q  = (const float*)d_in[0];
    const float* v  = (const float*)d_in[1];
    const float* k  = (const float*)d_in[2];
    const float* Wq = (const float*)d_in[3];
    const float* bq = (const float*)d_in[4];
    const float* Wk = (const float*)d_in[5];
    const float* bk = (const float*)d_in[6];
    const float* Wv = (const float*)d_in[7];
    const float* bv = (const float*)d_in[8];
    const float* Wo = (const float*)d_in[9];
    const float* bo = (const float*)d_in[10];

    float *qh, *kh, *vh, *ctx;
    __nv_bfloat16 *ah, *al, *wh, *wl;
    cudaGetSymbolAddress((void**)&qh,  g_qh);
    cudaGetSymbolAddress((void**)&kh,  g_kh);
    cudaGetSymbolAddress((void**)&vh,  g_vh);
    cudaGetSymbolAddress((void**)&ctx, g_ctx);
    cudaGetSymbolAddress((void**)&ah,  g_Ah);
    cudaGetSymbolAddress((void**)&al,  g_Al);
    cudaGetSymbolAddress((void**)&wh,  g_Wh);
    cudaGetSymbolAddress((void**)&wl,  g_Wl);

    cudaFuncSetAttribute(attn_kernel, cudaFuncAttributeMaxDynamicSharedMemorySize, ATTN_SMEM);
    cudaFuncSetAttribute(gemm_mma<1>, cudaFuncAttributeMaxDynamicSharedMemorySize, GEMM_SMEM);
    cudaFuncSetAttribute(gemm_mma<0>, cudaFuncAttributeMaxDynamicSharedMemorySize, GEMM_SMEM);

    const int nX4 = Mc * Hc / 4;
    const int nW4 = Hc * Hc / 4;
    dim3 tg(Hc / 128, Mc / 128);   // (8, 32)

    // Q projection
    split_kernel<<<(nX4 + 255) / 256, 256>>>(q, ah, al, nX4);
    split_kernel<<<(nW4 + 255) / 256, 256>>>(Wq, wh, wl, nW4);
    gemm_mma<1><<<tg, 256, GEMM_SMEM>>>(ah, al, wh, wl, bq, qh);
    // K projection
    split_kernel<<<(nX4 + 255) / 256, 256>>>(k, ah, al, nX4);
    split_kernel<<<(nW4 + 255) / 256, 256>>>(Wk, wh, wl, nW4);
    gemm_mma<1><<<tg, 256, GEMM_SMEM>>>(ah, al, wh, wl, bk, kh);
    // V projection
    split_kernel<<<(nX4 + 255) / 256, 256>>>(v, ah, al, nX4);
    split_kernel<<<(nW4 + 255) / 256, 256>>>(Wv, wh, wl, nW4);
    gemm_mma<1><<<tg, 256, GEMM_SMEM>>>(ah, al, wh, wl, bv, vh);

    // attention
    attn_kernel<<<dim3(Sc / 64, NHc, Bc), 256, ATTN_SMEM>>>(qh, kh, vh, ctx);

    // output projection
    split_kernel<<<(nX4 + 255) / 256, 256>>>(ctx, ah, al, nX4);
    split_kernel<<<(nW4 + 255) / 256, 256>>>(Wo, wh, wl, nW4);
    gemm_mma<0><<<tg, 256, GEMM_SMEM>>>(ah, al, wh, wl, bo, (float*)d_out);
}

// round 6
// speedup vs baseline: 2.5959x; 1.9373x over previous
#include <cuda_runtime.h>
#include <cuda_bf16.h>
#include <cstdint>
#include <cstddef>

// Problem constants
#define Bc  2
#define Sc  2048
#define Hc  1024
#define NHc 16
#define DKc 64
#define Mc  (Bc * Sc)   // 4096

// ---------------- mma.sync helpers ----------------
__device__ __forceinline__ uint32_t smem_u32(const void* p) {
    uint32_t a;
    asm("{ .reg .u64 t; cvta.to.shared.u64 t, %1; cvt.u32.u64 %0, t; }" : "=r"(a) : "l"(p));
    return a;
}
__device__ __forceinline__ void ldsm_x4(uint32_t* r, uint32_t a) {
    asm volatile("ldmatrix.sync.aligned.m8n8.x4.shared.b16 {%0,%1,%2,%3}, [%4];"
        : "=r"(r[0]), "=r"(r[1]), "=r"(r[2]), "=r"(r[3]) : "r"(a));
}
__device__ __forceinline__ void ldsm_x2(uint32_t* r, uint32_t a) {
    asm volatile("ldmatrix.sync.aligned.m8n8.x2.shared.b16 {%0,%1}, [%2];"
        : "=r"(r[0]), "=r"(r[1]) : "r"(a));
}
__device__ __forceinline__ void mma16816(float* c, const uint32_t* a, const uint32_t* b) {
    asm volatile("mma.sync.aligned.m16n8k16.row.col.f32.bf16.bf16.f32 "
        "{%0,%1,%2,%3}, {%4,%5,%6,%7}, {%8,%9}, {%0,%1,%2,%3};"
        : "+f"(c[0]), "+f"(c[1]), "+f"(c[2]), "+f"(c[3])
        : "r"(a[0]), "r"(a[1]), "r"(a[2]), "r"(a[3]), "r"(b[0]), "r"(b[1]));
}
__device__ __forceinline__ void cp_async16(uint32_t dst, const void* src) {
    asm volatile("cp.async.cg.shared.global [%0], [%1], 16;" :: "r"(dst), "l"(src));
}
#define CP_COMMIT() asm volatile("cp.async.commit_group;" ::: "memory")
#define CP_WAIT1()  asm volatile("cp.async.wait_group 1;" ::: "memory")
#define CP_WAIT0()  asm volatile("cp.async.wait_group 0;" ::: "memory")

// pack two fp32 -> bf16x2 (lo = first arg)
__device__ __forceinline__ uint32_t cvt2_bf16(float lo, float hi) {
    uint32_t r;
    asm("cvt.rn.bf16x2.f32 %0, %1, %2;" : "=r"(r) : "f"(hi), "f"(lo));
    return r;
}

// ---------------- device scratch (allocation-free) ----------------
__device__ __nv_bfloat16 g_Ah[Mc * Hc];
__device__ __nv_bfloat16 g_Al[Mc * Hc];
__device__ __nv_bfloat16 g_Wh[Hc * Hc];
__device__ __nv_bfloat16 g_Wl[Hc * Hc];
__device__ __nv_bfloat16 g_Qh[Bc * NHc * Sc * DKc];  // [b,h,s,d]
__device__ __nv_bfloat16 g_Ql[Bc * NHc * Sc * DKc];
__device__ __nv_bfloat16 g_Kh[Bc * NHc * Sc * DKc];  // [b,h,s,d]
__device__ __nv_bfloat16 g_Kl[Bc * NHc * Sc * DKc];
__device__ __nv_bfloat16 g_Vh[Bc * NHc * DKc * Sc];  // [b,h,d,s] (transposed)
__device__ __nv_bfloat16 g_Vl[Bc * NHc * DKc * Sc];
__device__ __nv_bfloat16 g_Ch[Mc * Hc];              // ctx [m][h*64+d]
__device__ __nv_bfloat16 g_Cl[Mc * Hc];

// ======================================================================
// fp32 -> bf16 hi/lo split
// ======================================================================
__global__ void split_kernel(const float* __restrict__ x,
                             __nv_bfloat16* __restrict__ hi,
                             __nv_bfloat16* __restrict__ lo, int n4)
{
    int i = blockIdx.x * blockDim.x + threadIdx.x;
    if (i >= n4) return;
    float4 v = ((const float4*)x)[i];
    uint32_t h0 = cvt2_bf16(v.x, v.y);
    uint32_t h1 = cvt2_bf16(v.z, v.w);
    ((uint32_t*)hi)[2 * i]     = h0;
    ((uint32_t*)hi)[2 * i + 1] = h1;
    float hx = __uint_as_float(h0 << 16),  hy = __uint_as_float(h0 & 0xffff0000u);
    float hz = __uint_as_float(h1 << 16),  hw = __uint_as_float(h1 & 0xffff0000u);
    ((uint32_t*)lo)[2 * i]     = cvt2_bf16(v.x - hx, v.y - hy);
    ((uint32_t*)lo)[2 * i + 1] = cvt2_bf16(v.z - hz, v.w - hw);
}

// ======================================================================
// mma.sync GEMM, 3-MMA bf16 split. CTA 128x128, 8 warps (2x4), BK=32.
// MODE 0: fp32 flat out. MODE 1: bf16 hi/lo [b,h,s,d]. MODE 2: bf16 hi/lo [b,h,d,s].
// ======================================================================
#define MSTR 40
#define TILE_B (128 * MSTR * 2)
#define STAGE_B (4 * TILE_B)
#define GEMM_SMEM (2 * STAGE_B)

template <int MODE>
__global__ void __launch_bounds__(256, 1) gemm_mma(
    const __nv_bfloat16* __restrict__ Ah, const __nv_bfloat16* __restrict__ Al,
    const __nv_bfloat16* __restrict__ Bh, const __nv_bfloat16* __restrict__ Bl,
    const float* __restrict__ bias, float* __restrict__ C,
    __nv_bfloat16* __restrict__ Oh, __nv_bfloat16* __restrict__ Ol)
{
    extern __shared__ char smem[];
    const uint32_t sb = smem_u32(smem);
    const int tid = threadIdx.x;
    const int wid = tid >> 5;
    const int lid = tid & 31;
    const int wm = (wid >> 2) * 64;
    const int wn = (wid & 3) * 32;
    const int m0 = blockIdx.y * 128;
    const int n0 = blockIdx.x * 128;

    const __nv_bfloat16* gsrc[4] = {
        Ah + (size_t)m0 * Hc, Al + (size_t)m0 * Hc,
        Bh + (size_t)n0 * Hc, Bl + (size_t)n0 * Hc };

    const int r0 = tid >> 2;
    const int c0 = tid & 3;

    auto stage_load = [&](int stage, int it) {
        uint32_t base = sb + stage * STAGE_B;
#pragma unroll
        for (int a = 0; a < 4; a++) {
            const __nv_bfloat16* s = gsrc[a] + it * 32;
#pragma unroll
            for (int rep = 0; rep < 2; rep++) {
                int row = r0 + rep * 64;
                cp_async16(base + a * TILE_B + row * (MSTR * 2) + c0 * 16,
                           s + (size_t)row * Hc + c0 * 8);
            }
        }
    };

    float acc[4][4][4] = {};

    stage_load(0, 0);
    CP_COMMIT();

    for (int it = 0; it < 32; it++) {
        if (it + 1 < 32) stage_load((it + 1) & 1, it + 1);
        CP_COMMIT();
        CP_WAIT1();
        __syncthreads();

        const uint32_t st = sb + (it & 1) * STAGE_B;
        const uint32_t sAh = st;
        const uint32_t sAl = st + TILE_B;
        const uint32_t sBh = st + 2 * TILE_B;
        const uint32_t sBl = st + 3 * TILE_B;

#pragma unroll
        for (int ks = 0; ks < 2; ks++) {
            const int k0 = ks * 16;
            uint32_t ah[4][4], al[4][4];
            const int ar = wm + (lid & 15);
            const int ak = k0 + ((lid >> 4) << 3);
#pragma unroll
            for (int mt = 0; mt < 4; mt++) {
                uint32_t off = (uint32_t)((ar + mt * 16) * MSTR + ak) * 2;
                ldsm_x4(ah[mt], sAh + off);
                ldsm_x4(al[mt], sAl + off);
            }
            uint32_t bh[4][2], bl[4][2];
            const int br = wn + (lid & 7);
            const int bk = k0 + (((lid >> 3) & 1) << 3);
#pragma unroll
            for (int nt = 0; nt < 4; nt++) {
                uint32_t off = (uint32_t)((br + nt * 8) * MSTR + bk) * 2;
                ldsm_x2(bh[nt], sBh + off);
                ldsm_x2(bl[nt], sBl + off);
            }
#pragma unroll
            for (int mt = 0; mt < 4; mt++) {
#pragma unroll
                for (int nt = 0; nt < 4; nt++) {
                    mma16816(acc[mt][nt], ah[mt], bh[nt]);
                    mma16816(acc[mt][nt], al[mt], bh[nt]);
                    mma16816(acc[mt][nt], ah[mt], bl[nt]);
                }
            }
        }
        __syncthreads();
    }

    // epilogue
    const int erow = (lid >> 2);
    const int ecol = (lid & 3) * 2;
#pragma unroll
    for (int mt = 0; mt < 4; mt++) {
#pragma unroll
        for (int nt = 0; nt < 4; nt++) {
            int m = m0 + wm + mt * 16 + erow;
            int n = n0 + wn + nt * 8 + ecol;
            float2 bi = *(const float2*)(bias + n);
            float e0 = acc[mt][nt][0] + bi.x, e1 = acc[mt][nt][1] + bi.y;  // row m
            float e2 = acc[mt][nt][2] + bi.x, e3 = acc[mt][nt][3] + bi.y;  // row m+8
            if (MODE == 0) {
                *(float2*)(C + (size_t)m * Hc + n) = make_float2(e0, e1);
                *(float2*)(C + (size_t)(m + 8) * Hc + n) = make_float2(e2, e3);
            } else if (MODE == 1) {
                int hidx = n >> 6, d = n & (DKc - 1);
                int bb = m >> 11, s = m & (Sc - 1);
                size_t i0 = (((size_t)bb * NHc + hidx) * Sc + s) * DKc + d;
                uint32_t h0 = cvt2_bf16(e0, e1);
                float f0 = __uint_as_float(h0 << 16), f1 = __uint_as_float(h0 & 0xffff0000u);
                ((uint32_t*)Oh)[i0 >> 1] = h0;
                ((uint32_t*)Ol)[i0 >> 1] = cvt2_bf16(e0 - f0, e1 - f1);
                int m2 = m + 8;
                int bb2 = m2 >> 11, s2 = m2 & (Sc - 1);
                size_t i1 = (((size_t)bb2 * NHc + hidx) * Sc + s2) * DKc + d;
                uint32_t h1 = cvt2_bf16(e2, e3);
                float f2 = __uint_as_float(h1 << 16), f3 = __uint_as_float(h1 & 0xffff0000u);
                ((uint32_t*)Oh)[i1 >> 1] = h1;
                ((uint32_t*)Ol)[i1 >> 1] = cvt2_bf16(e2 - f2, e3 - f3);
            } else {
                // MODE 2: transposed [b,h,d,s] bf16 hi/lo, scalar 2B stores
                int hidx = n >> 6, d = n & (DKc - 1);
                float ev[4] = {e0, e1, e2, e3};
#pragma unroll
                for (int q = 0; q < 4; q++) {
                    int mm = m + (q >> 1) * 8;
                    int dd = d + (q & 1);
                    int bb = mm >> 11, s = mm & (Sc - 1);
                    size_t ix = (((size_t)bb * NHc + hidx) * DKc + dd) * Sc + s;
                    __nv_bfloat16 hv = __float2bfloat16(ev[q]);
                    Oh[ix] = hv;
                    Ol[ix] = __float2bfloat16(ev[q] - __bfloat162float(hv));
                }
            }
        }
    }
}

// ======================================================================
// Flash attention on mma.sync, 3-MMA bf16 split both matmuls.
// CTA: 128 q-rows x (head,batch), 8 warps x m16, k-blocks of 64.
// Row stride 72 bf16 (144B): rows are 64 elems (128B) + 16B pad; ldmatrix
// phase = 9*row mod 8 = row mod 8 -> conflict-free.
// ======================================================================
#define ASTRD 72                        // bf16 elems per smem row (144B)
#define AROW_B (ASTRD * 2)              // 144 bytes
#define AKV_T (64 * AROW_B)             // 9216 bytes per KV tensor
#define AKV_B (4 * AKV_T)               // 36864 per stage (Kh,Kl,Vh,Vl)
#define AQ_T  (128 * AROW_B)            // 18432 per Q tensor
#define ATT_SMEM (2 * AKV_B)            // 73728

__global__ void __launch_bounds__(256) attn_mma(
    const __nv_bfloat16* __restrict__ Qh, const __nv_bfloat16* __restrict__ Ql,
    const __nv_bfloat16* __restrict__ Kh, const __nv_bfloat16* __restrict__ Kl,
    const __nv_bfloat16* __restrict__ Vh, const __nv_bfloat16* __restrict__ Vl,
    __nv_bfloat16* __restrict__ Ch, __nv_bfloat16* __restrict__ Cl)
{
    extern __shared__ char smem[];
    const uint32_t sb = smem_u32(smem);
    const int tid = threadIdx.x;
    const int wid = tid >> 5;
    const int lid = tid & 31;
    const int qt = blockIdx.x;
    const int h  = blockIdx.y;
    const int b  = blockIdx.z;
    const size_t bh = (size_t)b * NHc + h;

    const __nv_bfloat16* qbh = Qh + (bh * Sc + (size_t)qt * 128) * DKc;
    const __nv_bfloat16* qbl = Ql + (bh * Sc + (size_t)qt * 128) * DKc;
    const __nv_bfloat16* kbh = Kh + bh * Sc * DKc;
    const __nv_bfloat16* kbl = Kl + bh * Sc * DKc;
    const __nv_bfloat16* vbh = Vh + bh * DKc * Sc;
    const __nv_bfloat16* vbl = Vl + bh * DKc * Sc;

    // ---- stage Q (128x64 hi/lo) into smem, load frags, then free smem ----
#pragma unroll
    for (int it = 0; it < 4; it++) {
        int idx = it * 256 + tid;        // 1024 chunks per tensor (128 rows x 8)
        int row = idx >> 3, c = idx & 7;
        cp_async16(sb + row * AROW_B + c * 16, qbh + (size_t)row * DKc + c * 8);
        cp_async16(sb + AQ_T + row * AROW_B + c * 16, qbl + (size_t)row * DKc + c * 8);
    }
    CP_COMMIT(); CP_WAIT0();
    __syncthreads();

    uint32_t qfh[4][4], qfl[4][4];
    const int wq = wid * 16;
#pragma unroll
    for (int ks = 0; ks < 4; ks++) {
        uint32_t off = (uint32_t)((wq + (lid & 15)) * ASTRD + ks * 16 + ((lid >> 4) << 3)) * 2;
        ldsm_x4(qfh[ks], sb + off);
        ldsm_x4(qfl[ks], sb + AQ_T + off);
    }
    __syncthreads();

    float cacc[8][4] = {};
    float mrow[2] = {-INFINITY, -INFINITY};
    float lrow[2] = {0.0f, 0.0f};

    auto stage_kv = [&](int bufi, int kt) {
        uint32_t base = sb + bufi * AKV_B;
#pragma unroll
        for (int it = 0; it < 2; it++) {
            int idx = it * 256 + tid;    // 512 chunks per tensor (64 rows x 8)
            int row = idx >> 3, c = idx & 7;
            size_t gk = (size_t)(kt * 64 + row) * DKc + c * 8;
            cp_async16(base + row * AROW_B + c * 16, kbh + gk);
            cp_async16(base + AKV_T + row * AROW_B + c * 16, kbl + gk);
            size_t gv = (size_t)row * Sc + kt * 64 + c * 8;
            cp_async16(base + 2 * AKV_T + row * AROW_B + c * 16, vbh + gv);
            cp_async16(base + 3 * AKV_T + row * AROW_B + c * 16, vbl + gv);
        }
    };

    stage_kv(0, 0);
    CP_COMMIT();

    for (int kt = 0; kt < Sc / 64; kt++) {
        if (kt + 1 < Sc / 64) stage_kv((kt + 1) & 1, kt + 1);
        CP_COMMIT();
        CP_WAIT1();
        __syncthreads();
        const uint32_t st = sb + (kt & 1) * AKV_B;

        // ---- S = Q K^T (3-split), fragments sacc[nt][4] ----
        float sacc[8][4] = {};
#pragma unroll
        for (int ks = 0; ks < 4; ks++) {
#pragma unroll
            for (int ntp = 0; ntp < 4; ntp++) {
                uint32_t off = (uint32_t)((16 * ntp + (lid & 7) + ((lid >> 4) << 3)) * ASTRD
                                          + ks * 16 + (((lid >> 3) & 1) << 3)) * 2;
                uint32_t kf[4], kfl[4];
                ldsm_x4(kf, st + off);
                ldsm_x4(kfl, st + AKV_T + off);
                mma16816(sacc[2 * ntp],     qfh[ks], kf);
                mma16816(sacc[2 * ntp],     qfl[ks], kf);
                mma16816(sacc[2 * ntp],     qfh[ks], kfl);
                mma16816(sacc[2 * ntp + 1], qfh[ks], kf + 2);
                mma16816(sacc[2 * ntp + 1], qfl[ks], kf + 2);
                mma16816(sacc[2 * ntp + 1], qfh[ks], kfl + 2);
            }
        }

        // ---- online softmax on fragments (rows r=lid>>2 and r+8) ----
#pragma unroll
        for (int r = 0; r < 2; r++) {
            float mx = -INFINITY;
#pragma unroll
            for (int nt = 0; nt < 8; nt++) {
                sacc[nt][2 * r]     *= 0.125f;
                sacc[nt][2 * r + 1] *= 0.125f;
                mx = fmaxf(mx, fmaxf(sacc[nt][2 * r], sacc[nt][2 * r + 1]));
            }
            mx = fmaxf(mx, __shfl_xor_sync(0xffffffffu, mx, 1));
            mx = fmaxf(mx, __shfl_xor_sync(0xffffffffu, mx, 2));
            float mn = fmaxf(mrow[r], mx);
            float alpha = __expf(mrow[r] - mn);
            mrow[r] = mn;
            float sum = 0.0f;
#pragma unroll
            for (int nt = 0; nt < 8; nt++) {
                float p0 = __expf(sacc[nt][2 * r] - mn);
                float p1 = __expf(sacc[nt][2 * r + 1] - mn);
                sacc[nt][2 * r] = p0; sacc[nt][2 * r + 1] = p1;
                sum += p0 + p1;
            }
            sum += __shfl_xor_sync(0xffffffffu, sum, 1);
            sum += __shfl_xor_sync(0xffffffffu, sum, 2);
            lrow[r] = lrow[r] * alpha + sum;
#pragma unroll
            for (int nt = 0; nt < 8; nt++) {
                cacc[nt][2 * r]     *= alpha;
                cacc[nt][2 * r + 1] *= alpha;
            }
        }

        // ---- P fragments (C-frag -> A-frag remap, hi/lo split in regs) ----
        uint32_t pfh[4][4], pfl[4][4];
#pragma unroll
        for (int jk = 0; jk < 4; jk++) {
#pragma unroll
            for (int half = 0; half < 2; half++) {
                int nt = 2 * jk + half;
#pragma unroll
                for (int rr = 0; rr < 2; rr++) {
                    float p0 = sacc[nt][2 * rr], p1 = sacc[nt][2 * rr + 1];
                    uint32_t hh = cvt2_bf16(p0, p1);
                    float f0 = __uint_as_float(hh << 16);
                    float f1 = __uint_as_float(hh & 0xffff0000u);
                    pfh[jk][2 * half + rr] = hh;
                    pfl[jk][2 * half + rr] = cvt2_bf16(p0 - f0, p1 - f1);
                }
            }
        }

        // ---- ctx += P V (3-split), V from transposed smem tiles ----
#pragma unroll
        for (int dp = 0; dp < 4; dp++) {
#pragma unroll
            for (int jk = 0; jk < 4; jk++) {
                uint32_t off = (uint32_t)((16 * dp + (lid & 7) + ((lid >> 4) << 3)) * ASTRD
                                          + jk * 16 + (((lid >> 3) & 1) << 3)) * 2;
                uint32_t vf[4], vfl[4];
                ldsm_x4(vf, st + 2 * AKV_T + off);
                ldsm_x4(vfl, st + 3 * AKV_T + off);
                mma16816(cacc[2 * dp],     pfh[jk], vf);
                mma16816(cacc[2 * dp],     pfl[jk], vf);
                mma16816(cacc[2 * dp],     pfh[jk], vfl);
                mma16816(cacc[2 * dp + 1], pfh[jk], vf + 2);
                mma16816(cacc[2 * dp + 1], pfl[jk], vf + 2);
                mma16816(cacc[2 * dp + 1], pfh[jk], vfl + 2);
            }
        }
        __syncthreads();
    }

    // ---- epilogue: normalize, split hi/lo, write ctx [m][h*64+d] ----
    const int s0 = qt * 128 + wq + (lid >> 2);
    const float inv0 = 1.0f / lrow[0];
    const float inv1 = 1.0f / lrow[1];
    const size_t base0 = ((size_t)b * Sc + s0) * Hc + h * DKc;
    const size_t base1 = base0 + 8 * (size_t)Hc;
#pragma unroll
    for (int nt = 0; nt < 8; nt++) {
        int d = 8 * nt + 2 * (lid & 3);
        float e0 = cacc[nt][0] * inv0, e1 = cacc[nt][1] * inv0;
        uint32_t hh = cvt2_bf16(e0, e1);
        float f0 = __uint_as_float(hh << 16), f1 = __uint_as_float(hh & 0xffff0000u);
        ((uint32_t*)Ch)[(base0 + d) >> 1] = hh;
        ((uint32_t*)Cl)[(base0 + d) >> 1] = cvt2_bf16(e0 - f0, e1 - f1);
        float e2 = cacc[nt][2] * inv1, e3 = cacc[nt][3] * inv1;
        uint32_t h2 = cvt2_bf16(e2, e3);
        float f2 = __uint_as_float(h2 << 16), f3 = __uint_as_float(h2 & 0xffff0000u);
        ((uint32_t*)Ch)[(base1 + d) >> 1] = h2;
        ((uint32_t*)Cl)[(base1 + d) >> 1] = cvt2_bf16(e2 - f2, e3 - f3);
    }
}

// ======================================================================
// launch
// ======================================================================
extern "C" void kernel_launch(void* const* d_in, const int* in_sizes, int n_in,
                              void* d_out, int out_size)
{
    (void)in_sizes; (void)n_in; (void)out_size;

    const float* q  = (const float*)d_in[0];
    const float* v  = (const float*)d_in[1];
    const float* k  = (const float*)d_in[2];
    const float* Wq = (const float*)d_in[3];
    const float* bq = (const float*)d_in[4];
    const float* Wk = (const float*)d_in[5];
    const float* bk = (const float*)d_in[6];
    const float* Wv = (const float*)d_in[7];
    const float* bv = (const float*)d_in[8];
    const float* Wo = (const float*)d_in[9];
    const float* bo = (const float*)d_in[10];

    __nv_bfloat16 *ah, *al, *wh, *wl, *qh, *ql, *kh, *kl, *vh, *vl, *ch, *cl;
    cudaGetSymbolAddress((void**)&ah, g_Ah);
    cudaGetSymbolAddress((void**)&al, g_Al);
    cudaGetSymbolAddress((void**)&wh, g_Wh);
    cudaGetSymbolAddress((void**)&wl, g_Wl);
    cudaGetSymbolAddress((void**)&qh, g_Qh);
    cudaGetSymbolAddress((void**)&ql, g_Ql);
    cudaGetSymbolAddress((void**)&kh, g_Kh);
    cudaGetSymbolAddress((void**)&kl, g_Kl);
    cudaGetSymbolAddress((void**)&vh, g_Vh);
    cudaGetSymbolAddress((void**)&vl, g_Vl);
    cudaGetSymbolAddress((void**)&ch, g_Ch);
    cudaGetSymbolAddress((void**)&cl, g_Cl);

    cudaFuncSetAttribute(gemm_mma<0>, cudaFuncAttributeMaxDynamicSharedMemorySize, GEMM_SMEM);
    cudaFuncSetAttribute(gemm_mma<1>, cudaFuncAttributeMaxDynamicSharedMemorySize, GEMM_SMEM);
    cudaFuncSetAttribute(gemm_mma<2>, cudaFuncAttributeMaxDynamicSharedMemorySize, GEMM_SMEM);
    cudaFuncSetAttribute(attn_mma, cudaFuncAttributeMaxDynamicSharedMemorySize, ATT_SMEM);

    const int nX4 = Mc * Hc / 4;
    const int nW4 = Hc * Hc / 4;
    dim3 tg(Hc / 128, Mc / 128);   // (8, 32)

    // Q projection -> bf16 hi/lo [b,h,s,d]
    split_kernel<<<(nX4 + 255) / 256, 256>>>(q, ah, al, nX4);
    split_kernel<<<(nW4 + 255) / 256, 256>>>(Wq, wh, wl, nW4);
    gemm_mma<1><<<tg, 256, GEMM_SMEM>>>(ah, al, wh, wl, bq, nullptr, qh, ql);
    // K projection -> bf16 hi/lo [b,h,s,d]
    split_kernel<<<(nX4 + 255) / 256, 256>>>(k, ah, al, nX4);
    split_kernel<<<(nW4 + 255) / 256, 256>>>(Wk, wh, wl, nW4);
    gemm_mma<1><<<tg, 256, GEMM_SMEM>>>(ah, al, wh, wl, bk, nullptr, kh, kl);
    // V projection -> bf16 hi/lo transposed [b,h,d,s]
    split_kernel<<<(nX4 + 255) / 256, 256>>>(v, ah, al, nX4);
    split_kernel<<<(nW4 + 255) / 256, 256>>>(Wv, wh, wl, nW4);
    gemm_mma<2><<<tg, 256, GEMM_SMEM>>>(ah, al, wh, wl, bv, nullptr, vh, vl);

    // attention -> ctx bf16 hi/lo
    attn_mma<<<dim3(Sc / 128, NHc, Bc), 256, ATT_SMEM>>>(qh, ql, kh, kl, vh, vl, ch, cl);

    // output projection (consumes ctx hi/lo directly)
    split_kernel<<<(nW4 + 255) / 256, 256>>>(Wo, wh, wl, nW4);
    gemm_mma<0><<<tg, 256, GEMM_SMEM>>>(ch, cl, wh, wl, bo, (float*)d_out, nullptr, nullptr);
}